// round 7
// baseline (speedup 1.0000x reference)
#include <cuda_runtime.h>

#define MAXN 100000
#define MAXE 1000000
#define MAXG 1024

// ---------------- scratch (device globals: no allocation allowed) ----------------
__device__ int   g_idx64;           // 1 if edge_index/batch are int64, 0 if int32
__device__ int   g_degcnt[MAXN];
__device__ int   g_cursor[MAXN];
__device__ int   g_rowptr[MAXN + 1];
__device__ int   g_col[MAXE];
__device__ float g_dinv[MAXN];
__device__ float g_selfc[MAXN];
__device__ float g_y[MAXN * 128];   // aggregation output (GEMM input)
__device__ float g_h[MAXN * 128];   // GEMM output (h1, then h2)
__device__ float g_psum[MAXG * 128];
__device__ float g_gcnt[MAXG];

// ---------------- small helpers ----------------
__device__ __forceinline__ float lo32(unsigned long long v) { return __uint_as_float((unsigned)v); }
__device__ __forceinline__ float hi32(unsigned long long v) { return __uint_as_float((unsigned)(v >> 32)); }

#define FMA2(d, a, b, c) asm("fma.rn.f32x2 %0, %1, %2, %3;" : "=l"(d) : "l"(a), "l"(b), "l"(c))
#define SPLAT2(d, s)     asm("mov.b64 %0, {%1, %1};" : "=l"(d) : "r"(__float_as_uint(s)))

__device__ __forceinline__ void vfma(float4& a, float4 v, float s) {
    a.x = fmaf(v.x, s, a.x); a.y = fmaf(v.y, s, a.y);
    a.z = fmaf(v.z, s, a.z); a.w = fmaf(v.w, s, a.w);
}
__device__ __forceinline__ void vfma(float2& a, float2 v, float s) {
    a.x = fmaf(v.x, s, a.x); a.y = fmaf(v.y, s, a.y);
}
__device__ __forceinline__ float4 vscale(float4 v, float s) { return make_float4(v.x*s, v.y*s, v.z*s, v.w*s); }
__device__ __forceinline__ float2 vscale(float2 v, float s) { return make_float2(v.x*s, v.y*s); }

// read element i of an index array that is either int32 or int64
__device__ __forceinline__ int idx_at(const void* p, int i) {
    return g_idx64 ? (int)((const long long*)p)[i] : ((const int*)p)[i];
}

// ---------------- dtype detection ----------------
// int64 (little-endian, values in [0, 2^31)) => every odd 32-bit word is 0.
// int32 random node ids in [0, N): odd words are node ids, ~never all zero.
__global__ void k_detect(const unsigned* __restrict__ ei) {
    unsigned o = ei[1] | ei[3] | ei[5] | ei[7] | ei[9] | ei[11] | ei[13] | ei[15];
    g_idx64 = (o == 0u) ? 1 : 0;
}

// ---------------- setup kernels ----------------
__global__ void k_zero(int N, int G) {
    int i = blockIdx.x * blockDim.x + threadIdx.x;
    if (i < N) { g_degcnt[i] = 0; g_cursor[i] = 0; }
    if (i < G * 128) g_psum[i] = 0.f;
    if (i < G) g_gcnt[i] = 0.f;
}

__global__ void k_count(const void* __restrict__ ei, int E) {
    int e = blockIdx.x * blockDim.x + threadIdx.x;
    if (e < E) {
        int d = idx_at(ei, E + e);   // dst row of edge_index
        atomicAdd(&g_degcnt[d], 1);
    }
}

// exclusive scan of g_degcnt[0..N) into g_rowptr[0..N]
__global__ void k_scan(int N) {
    __shared__ int ss[1024];
    int tid = threadIdx.x;
    int chunk = (N + 1023) >> 10;
    int s0 = tid * chunk;
    int s1 = min(s0 + chunk, N);
    int s = 0;
    for (int i = s0; i < s1; i++) s += g_degcnt[i];
    ss[tid] = s;
    __syncthreads();
    for (int off = 1; off < 1024; off <<= 1) {
        int v = (tid >= off) ? ss[tid - off] : 0;
        __syncthreads();
        ss[tid] += v;
        __syncthreads();
    }
    int run = (tid == 0) ? 0 : ss[tid - 1];
    for (int i = s0; i < s1; i++) { g_rowptr[i] = run; run += g_degcnt[i]; }
    if (tid == 1023) g_rowptr[N] = ss[1023];
}

__global__ void k_dinv(int N) {
    int i = blockIdx.x * blockDim.x + threadIdx.x;
    if (i < N) {
        float d = (float)g_degcnt[i] + 1.0f;
        g_dinv[i]  = rsqrtf(d);
        g_selfc[i] = 1.0f / d;
    }
}

__global__ void k_fill(const void* __restrict__ ei, int E) {
    int e = blockIdx.x * blockDim.x + threadIdx.x;
    if (e < E) {
        int s = idx_at(ei, e);       // src row
        int d = idx_at(ei, E + e);   // dst row
        int pos = g_rowptr[d] + atomicAdd(&g_cursor[d], 1);
        g_col[pos] = s;
    }
}

// ---------------- aggregation: g_y[i] = selfc[i]*x[i] + sum_{e: dst=i} dinv[src]*dinv[i]*x[src]
// one warp per node. FROM_GH: read features from g_h (layer 2) instead of the xin param.
template <typename VecT, bool FROM_GH>
__global__ void k_agg(const float* __restrict__ xin, int N) {
    int t = blockIdx.x * blockDim.x + threadIdx.x;
    int node = t >> 5;
    int lane = t & 31;
    if (node >= N) return;
    const VecT* __restrict__ xv = FROM_GH ? (const VecT*)g_h : (const VecT*)xin;
    VecT a = vscale(xv[node * 32 + lane], g_selfc[node]);
    float di = g_dinv[node];
    int p = g_rowptr[node];
    int e = g_rowptr[node + 1];
    for (; p + 1 < e; p += 2) {
        int s0 = __ldg(&g_col[p]);
        int s1 = __ldg(&g_col[p + 1]);
        float w0 = di * __ldg(&g_dinv[s0]);
        float w1 = di * __ldg(&g_dinv[s1]);
        VecT v0 = xv[s0 * 32 + lane];
        VecT v1 = xv[s1 * 32 + lane];
        vfma(a, v0, w0);
        vfma(a, v1, w1);
    }
    if (p < e) {
        int s0 = __ldg(&g_col[p]);
        vfma(a, xv[s0 * 32 + lane], di * __ldg(&g_dinv[s0]));
    }
    ((VecT*)g_y)[node * 32 + lane] = a;
}

// ---------------- GEMM: g_h[N,128] = relu(g_y[N,K] @ W[K,128] + b), f32x2 packed
// 64 rows x 128 cols per block, 256 threads, K chunked by 32 (static smem ~24.4KB).
// Thread tile: 8 rows x 4 cols; row-pairs packed in f32x2 accumulators.
template <int K>
__global__ void k_gemm(const float* __restrict__ W, const float* __restrict__ bias, int N) {
    __shared__ float w_s[32 * 128];   // W chunk  [32][128]
    __shared__ float x_s[32 * 66];    // x^T chunk [32][64+2pad]
    const int tid  = threadIdx.x;
    const int row0 = blockIdx.x * 64;
    const int tc = tid & 31;          // lane -> col group (4 cols)
    const int tr = tid >> 5;          // warp -> row group (8 rows)
    const int r0 = tr * 8;
    const int c0 = tc * 4;

    unsigned long long acc[4][4];
#pragma unroll
    for (int p = 0; p < 4; p++)
#pragma unroll
        for (int c = 0; c < 4; c++) acc[p][c] = 0ull;

    for (int kc = 0; kc < K; kc += 32) {
        __syncthreads();   // previous chunk fully consumed before overwrite
        // load W chunk (32 x 128)
        {
            const float4* W4 = (const float4*)(W + kc * 128);
            float4* ws4 = (float4*)w_s;
#pragma unroll
            for (int i = 0; i < 4; i++) ws4[tid + 256 * i] = W4[tid + 256 * i];
        }
        // load x chunk transposed: rows row0..row0+63, k = kc..kc+31
        {
            int kq = tid & 7;          // which float4 within the 32-wide chunk
            int rb = tid >> 3;         // 32 rows per pass
#pragma unroll
            for (int rr = 0; rr < 2; rr++) {
                int r = rb + 32 * rr;
                int row = row0 + r;
                float4 xv = (row < N) ? ((const float4*)g_y)[(row * K + kc) / 4 + kq]
                                      : make_float4(0.f, 0.f, 0.f, 0.f);
                x_s[(4 * kq + 0) * 66 + r] = xv.x;
                x_s[(4 * kq + 1) * 66 + r] = xv.y;
                x_s[(4 * kq + 2) * 66 + r] = xv.z;
                x_s[(4 * kq + 3) * 66 + r] = xv.w;
            }
        }
        __syncthreads();

#pragma unroll 4
        for (int k = 0; k < 32; k++) {
            const float* xr = x_s + k * 66 + r0;
            unsigned long long xp0 = *(const unsigned long long*)(xr + 0);
            unsigned long long xp1 = *(const unsigned long long*)(xr + 2);
            unsigned long long xp2 = *(const unsigned long long*)(xr + 4);
            unsigned long long xp3 = *(const unsigned long long*)(xr + 6);
            float4 wv = *(const float4*)(w_s + k * 128 + c0);
            unsigned long long wb0, wb1, wb2, wb3;
            SPLAT2(wb0, wv.x); SPLAT2(wb1, wv.y); SPLAT2(wb2, wv.z); SPLAT2(wb3, wv.w);
            FMA2(acc[0][0], xp0, wb0, acc[0][0]); FMA2(acc[0][1], xp0, wb1, acc[0][1]);
            FMA2(acc[0][2], xp0, wb2, acc[0][2]); FMA2(acc[0][3], xp0, wb3, acc[0][3]);
            FMA2(acc[1][0], xp1, wb0, acc[1][0]); FMA2(acc[1][1], xp1, wb1, acc[1][1]);
            FMA2(acc[1][2], xp1, wb2, acc[1][2]); FMA2(acc[1][3], xp1, wb3, acc[1][3]);
            FMA2(acc[2][0], xp2, wb0, acc[2][0]); FMA2(acc[2][1], xp2, wb1, acc[2][1]);
            FMA2(acc[2][2], xp2, wb2, acc[2][2]); FMA2(acc[2][3], xp2, wb3, acc[2][3]);
            FMA2(acc[3][0], xp3, wb0, acc[3][0]); FMA2(acc[3][1], xp3, wb1, acc[3][1]);
            FMA2(acc[3][2], xp3, wb2, acc[3][2]); FMA2(acc[3][3], xp3, wb3, acc[3][3]);
        }
    }

    float4 bv = ((const float4*)bias)[tc];
#pragma unroll
    for (int rr = 0; rr < 8; rr++) {
        int row = row0 + r0 + rr;
        if (row < N) {
            int p = rr >> 1;
            float4 o;
            if (rr & 1) {
                o.x = hi32(acc[p][0]); o.y = hi32(acc[p][1]); o.z = hi32(acc[p][2]); o.w = hi32(acc[p][3]);
            } else {
                o.x = lo32(acc[p][0]); o.y = lo32(acc[p][1]); o.z = lo32(acc[p][2]); o.w = lo32(acc[p][3]);
            }
            o.x = fmaxf(o.x + bv.x, 0.f);
            o.y = fmaxf(o.y + bv.y, 0.f);
            o.z = fmaxf(o.z + bv.z, 0.f);
            o.w = fmaxf(o.w + bv.w, 0.f);
            ((float4*)g_h)[row * 32 + tc] = o;
        }
    }
}

// ---------------- pooling: batch is sorted; per-block local accumulation + flush atomics ----
__global__ void k_pool(const void* __restrict__ batch, int N) {
    int c = threadIdx.x;            // 0..127, feature column
    int n0 = blockIdx.x * 128;
    if (n0 >= N) return;
    int n1 = min(n0 + 128, N);
    int curg = idx_at(batch, n0);
    float acc = 0.f, cntacc = 0.f;
    for (int n = n0; n < n1; n++) {
        int g = idx_at(batch, n);
        if (g != curg) {
            atomicAdd(&g_psum[curg * 128 + c], acc);
            if (c == 0) atomicAdd(&g_gcnt[curg], cntacc);
            acc = 0.f; cntacc = 0.f; curg = g;
        }
        acc += g_h[n * 128 + c];
        cntacc += 1.f;
    }
    atomicAdd(&g_psum[curg * 128 + c], acc);
    if (c == 0) atomicAdd(&g_gcnt[curg], cntacc);
}

// ---------------- final FC (128 -> 2) + softmax ----------------
__global__ void k_fc(const float* __restrict__ Wfc, const float* __restrict__ bfc,
                     float* __restrict__ out, int G) {
    int g = blockIdx.x * blockDim.x + threadIdx.x;
    if (g >= G) return;
    float inv = 1.0f / fmaxf(g_gcnt[g], 1.0f);
    float l0 = bfc[0], l1 = bfc[1];
#pragma unroll 8
    for (int c = 0; c < 128; c++) {
        float p = g_psum[g * 128 + c] * inv;
        l0 = fmaf(p, Wfc[2 * c + 0], l0);
        l1 = fmaf(p, Wfc[2 * c + 1], l1);
    }
    float m = fmaxf(l0, l1);
    float e0 = __expf(l0 - m), e1 = __expf(l1 - m);
    float s = e0 + e1;
    out[2 * g + 0] = e0 / s;
    out[2 * g + 1] = e1 / s;
}

// ---------------- launch: ONLY kernel launches, no other runtime APIs ----------------
extern "C" void kernel_launch(void* const* d_in, const int* in_sizes, int n_in,
                              void* d_out, int out_size) {
    // Fixed positional prefix per metadata order: x, edge_index, batch, ...
    const float* x     = (const float*)d_in[0];
    const void*  ei    = d_in[1];
    const void*  batch = d_in[2];

    // Weights identified by SIZE (robust to num_graphs being materialized or not):
    // W1: 64*128=8192, b1: 128 (first), W2: 128*128=16384, b2: 128 (second),
    // Wfc: 128*2=256, bfc: 2, num_graphs scalar: 1 (skipped).
    const float *W1 = 0, *b1 = 0, *W2 = 0, *b2 = 0, *Wfc = 0, *bfc = 0;
    for (int i = 3; i < n_in; i++) {
        int s = in_sizes[i];
        const float* p = (const float*)d_in[i];
        if      (s == 8192)  W1 = p;
        else if (s == 16384) W2 = p;
        else if (s == 256)   Wfc = p;
        else if (s == 2)     bfc = p;
        else if (s == 128)   { if (!b1) b1 = p; else b2 = p; }
        // s == 1: num_graphs scalar — ignored (G comes from out_size)
    }

    int N = in_sizes[2];        // batch has one entry per node
    int E = in_sizes[1] / 2;    // edge_index is [2, E]
    int G = out_size / 2;

    k_detect<<<1, 1>>>((const unsigned*)ei);

    int nzero = N > G * 128 ? N : G * 128;
    k_zero<<<(nzero + 255) / 256, 256>>>(N, G);

    // CSR build (by dst) + norm coefficients
    k_count<<<(E + 255) / 256, 256>>>(ei, E);
    k_scan<<<1, 1024>>>(N);
    k_dinv<<<(N + 255) / 256, 256>>>(N);
    k_fill<<<(E + 255) / 256, 256>>>(ei, E);

    int aggBlocks  = (N * 32 + 255) / 256;
    int gemmBlocks = (N + 63) / 64;

    // layer 1: g_y = A_hat x (N x 64), g_h = relu(g_y W1 + b1)
    k_agg<float2, false><<<aggBlocks, 256>>>(x, N);
    k_gemm<64><<<gemmBlocks, 256>>>(W1, b1, N);

    // layer 2: g_y = A_hat g_h (N x 128), g_h = relu(g_y W2 + b2)
    k_agg<float4, true><<<aggBlocks, 256>>>(nullptr, N);
    k_gemm<128><<<gemmBlocks, 256>>>(W2, b2, N);

    // pooling + FC + softmax
    k_pool<<<(N + 127) / 128, 128>>>(batch, N);
    k_fc<<<(G + 127) / 128, 128>>>(Wfc, bfc, out_size ? (float*)d_out : nullptr, G);
}

// round 8
// speedup vs baseline: 1.2958x; 1.2958x over previous
#include <cuda_runtime.h>

#define MAXN 100000
#define MAXE 1000000
#define MAXG 1024
#define SCAN_T 512

// ---------------- scratch (device globals: no allocation allowed) ----------------
__device__ int   g_idx64;           // 1 if edge_index/batch are int64, 0 if int32
__device__ int   g_degcnt[MAXN];
__device__ int   g_cursor[MAXN];
__device__ int   g_rowptr[MAXN + 1];
__device__ int   g_bsum[256];       // per-block sums for the device-wide scan
__device__ int   g_col[MAXE];
__device__ float g_dinv[MAXN];
__device__ float g_selfc[MAXN];
__device__ float g_y[MAXN * 128];   // aggregation output (GEMM input)
__device__ float g_h[MAXN * 128];   // GEMM output (h1, then h2)
__device__ float g_psum[MAXG * 128];
__device__ float g_gcnt[MAXG];

// ---------------- small helpers ----------------
__device__ __forceinline__ float lo32(unsigned long long v) { return __uint_as_float((unsigned)v); }
__device__ __forceinline__ float hi32(unsigned long long v) { return __uint_as_float((unsigned)(v >> 32)); }

#define FMA2(d, a, b, c) asm("fma.rn.f32x2 %0, %1, %2, %3;" : "=l"(d) : "l"(a), "l"(b), "l"(c))
#define SPLAT2(d, s)     asm("mov.b64 %0, {%1, %1};" : "=l"(d) : "r"(__float_as_uint(s)))

__device__ __forceinline__ void vfma(float4& a, float4 v, float s) {
    a.x = fmaf(v.x, s, a.x); a.y = fmaf(v.y, s, a.y);
    a.z = fmaf(v.z, s, a.z); a.w = fmaf(v.w, s, a.w);
}
__device__ __forceinline__ void vfma(float2& a, float2 v, float s) {
    a.x = fmaf(v.x, s, a.x); a.y = fmaf(v.y, s, a.y);
}
__device__ __forceinline__ float4 vscale(float4 v, float s) { return make_float4(v.x*s, v.y*s, v.z*s, v.w*s); }
__device__ __forceinline__ float2 vscale(float2 v, float s) { return make_float2(v.x*s, v.y*s); }

// read element i of an index array that is either int32 or int64
__device__ __forceinline__ int idx_at(const void* p, int i) {
    return g_idx64 ? (int)((const long long*)p)[i] : ((const int*)p)[i];
}

// ---------------- dtype detection ----------------
__global__ void k_detect(const unsigned* __restrict__ ei) {
    unsigned o = ei[1] | ei[3] | ei[5] | ei[7] | ei[9] | ei[11] | ei[13] | ei[15];
    g_idx64 = (o == 0u) ? 1 : 0;
}

// ---------------- setup kernels ----------------
__global__ void k_zero(int N, int G) {
    int i = blockIdx.x * blockDim.x + threadIdx.x;
    if (i < N) { g_degcnt[i] = 0; g_cursor[i] = 0; }
    if (i < G * 128) g_psum[i] = 0.f;
    if (i < G) g_gcnt[i] = 0.f;
}

__global__ void k_count(const void* __restrict__ ei, int E) {
    int e = blockIdx.x * blockDim.x + threadIdx.x;
    if (e < E) {
        int d = idx_at(ei, E + e);   // dst row of edge_index
        atomicAdd(&g_degcnt[d], 1);
    }
}

// ---------------- device-wide exclusive scan of g_degcnt into g_rowptr ----------------
// phase 1: per-block sums
__global__ void k_scan1(int N) {
    __shared__ int ss[SCAN_T];
    int tid = threadIdx.x;
    int i = blockIdx.x * SCAN_T + tid;
    ss[tid] = (i < N) ? g_degcnt[i] : 0;
    __syncthreads();
#pragma unroll
    for (int off = SCAN_T / 2; off > 0; off >>= 1) {
        if (tid < off) ss[tid] += ss[tid + off];
        __syncthreads();
    }
    if (tid == 0) g_bsum[blockIdx.x] = ss[0];
}

// phase 2: exclusive scan of block sums (nb <= 256), also writes rowptr[N] = total
__global__ void k_scan2(int nb, int N) {
    __shared__ int ss[256];
    int tid = threadIdx.x;
    int v = (tid < nb) ? g_bsum[tid] : 0;
    ss[tid] = v;
    __syncthreads();
#pragma unroll
    for (int off = 1; off < 256; off <<= 1) {
        int t = (tid >= off) ? ss[tid - off] : 0;
        __syncthreads();
        ss[tid] += t;
        __syncthreads();
    }
    if (tid < nb) g_bsum[tid] = ss[tid] - v;     // exclusive prefix of block sums
    if (tid == 255) g_rowptr[N] = ss[255];
}

// phase 3: block-local exclusive scan + block offset
__global__ void k_scan3(int N) {
    __shared__ int ss[SCAN_T];
    int tid = threadIdx.x;
    int i = blockIdx.x * SCAN_T + tid;
    int v = (i < N) ? g_degcnt[i] : 0;
    ss[tid] = v;
    __syncthreads();
#pragma unroll
    for (int off = 1; off < SCAN_T; off <<= 1) {
        int t = (tid >= off) ? ss[tid - off] : 0;
        __syncthreads();
        ss[tid] += t;
        __syncthreads();
    }
    if (i < N) g_rowptr[i] = g_bsum[blockIdx.x] + ss[tid] - v;
}

__global__ void k_dinv(int N) {
    int i = blockIdx.x * blockDim.x + threadIdx.x;
    if (i < N) {
        float d = (float)g_degcnt[i] + 1.0f;
        g_dinv[i]  = rsqrtf(d);
        g_selfc[i] = 1.0f / d;
    }
}

__global__ void k_fill(const void* __restrict__ ei, int E) {
    int e = blockIdx.x * blockDim.x + threadIdx.x;
    if (e < E) {
        int s = idx_at(ei, e);       // src row
        int d = idx_at(ei, E + e);   // dst row
        int pos = g_rowptr[d] + atomicAdd(&g_cursor[d], 1);
        g_col[pos] = s;
    }
}

// ---------------- aggregation: g_y[i] = selfc[i]*x[i] + sum_{e: dst=i} dinv[src]*dinv[i]*x[src]
// one warp per node. FROM_GH: read features from g_h (layer 2) instead of the xin param.
template <typename VecT, bool FROM_GH>
__global__ void k_agg(const float* __restrict__ xin, int N) {
    int t = blockIdx.x * blockDim.x + threadIdx.x;
    int node = t >> 5;
    int lane = t & 31;
    if (node >= N) return;
    const VecT* __restrict__ xv = FROM_GH ? (const VecT*)g_h : (const VecT*)xin;
    VecT a = vscale(xv[node * 32 + lane], g_selfc[node]);
    float di = g_dinv[node];
    int p = g_rowptr[node];
    int e = g_rowptr[node + 1];
    for (; p + 1 < e; p += 2) {
        int s0 = __ldg(&g_col[p]);
        int s1 = __ldg(&g_col[p + 1]);
        float w0 = di * __ldg(&g_dinv[s0]);
        float w1 = di * __ldg(&g_dinv[s1]);
        VecT v0 = xv[s0 * 32 + lane];
        VecT v1 = xv[s1 * 32 + lane];
        vfma(a, v0, w0);
        vfma(a, v1, w1);
    }
    if (p < e) {
        int s0 = __ldg(&g_col[p]);
        vfma(a, xv[s0 * 32 + lane], di * __ldg(&g_dinv[s0]));
    }
    ((VecT*)g_y)[node * 32 + lane] = a;
}

// ---------------- GEMM: g_h[N,128] = relu(g_y[N,K] @ W[K,128] + b), f32x2 packed
template <int K>
__global__ void k_gemm(const float* __restrict__ W, const float* __restrict__ bias, int N) {
    __shared__ float w_s[32 * 128];   // W chunk  [32][128]
    __shared__ float x_s[32 * 66];    // x^T chunk [32][64+2pad]
    const int tid  = threadIdx.x;
    const int row0 = blockIdx.x * 64;
    const int tc = tid & 31;          // lane -> col group (4 cols)
    const int tr = tid >> 5;          // warp -> row group (8 rows)
    const int r0 = tr * 8;
    const int c0 = tc * 4;

    unsigned long long acc[4][4];
#pragma unroll
    for (int p = 0; p < 4; p++)
#pragma unroll
        for (int c = 0; c < 4; c++) acc[p][c] = 0ull;

    for (int kc = 0; kc < K; kc += 32) {
        __syncthreads();   // previous chunk fully consumed before overwrite
        {
            const float4* W4 = (const float4*)(W + kc * 128);
            float4* ws4 = (float4*)w_s;
#pragma unroll
            for (int i = 0; i < 4; i++) ws4[tid + 256 * i] = W4[tid + 256 * i];
        }
        {
            int kq = tid & 7;
            int rb = tid >> 3;
#pragma unroll
            for (int rr = 0; rr < 2; rr++) {
                int r = rb + 32 * rr;
                int row = row0 + r;
                float4 xv = (row < N) ? ((const float4*)g_y)[(row * K + kc) / 4 + kq]
                                      : make_float4(0.f, 0.f, 0.f, 0.f);
                x_s[(4 * kq + 0) * 66 + r] = xv.x;
                x_s[(4 * kq + 1) * 66 + r] = xv.y;
                x_s[(4 * kq + 2) * 66 + r] = xv.z;
                x_s[(4 * kq + 3) * 66 + r] = xv.w;
            }
        }
        __syncthreads();

#pragma unroll 4
        for (int k = 0; k < 32; k++) {
            const float* xr = x_s + k * 66 + r0;
            unsigned long long xp0 = *(const unsigned long long*)(xr + 0);
            unsigned long long xp1 = *(const unsigned long long*)(xr + 2);
            unsigned long long xp2 = *(const unsigned long long*)(xr + 4);
            unsigned long long xp3 = *(const unsigned long long*)(xr + 6);
            float4 wv = *(const float4*)(w_s + k * 128 + c0);
            unsigned long long wb0, wb1, wb2, wb3;
            SPLAT2(wb0, wv.x); SPLAT2(wb1, wv.y); SPLAT2(wb2, wv.z); SPLAT2(wb3, wv.w);
            FMA2(acc[0][0], xp0, wb0, acc[0][0]); FMA2(acc[0][1], xp0, wb1, acc[0][1]);
            FMA2(acc[0][2], xp0, wb2, acc[0][2]); FMA2(acc[0][3], xp0, wb3, acc[0][3]);
            FMA2(acc[1][0], xp1, wb0, acc[1][0]); FMA2(acc[1][1], xp1, wb1, acc[1][1]);
            FMA2(acc[1][2], xp1, wb2, acc[1][2]); FMA2(acc[1][3], xp1, wb3, acc[1][3]);
            FMA2(acc[2][0], xp2, wb0, acc[2][0]); FMA2(acc[2][1], xp2, wb1, acc[2][1]);
            FMA2(acc[2][2], xp2, wb2, acc[2][2]); FMA2(acc[2][3], xp2, wb3, acc[2][3]);
            FMA2(acc[3][0], xp3, wb0, acc[3][0]); FMA2(acc[3][1], xp3, wb1, acc[3][1]);
            FMA2(acc[3][2], xp3, wb2, acc[3][2]); FMA2(acc[3][3], xp3, wb3, acc[3][3]);
        }
    }

    float4 bv = ((const float4*)bias)[tc];
#pragma unroll
    for (int rr = 0; rr < 8; rr++) {
        int row = row0 + r0 + rr;
        if (row < N) {
            int p = rr >> 1;
            float4 o;
            if (rr & 1) {
                o.x = hi32(acc[p][0]); o.y = hi32(acc[p][1]); o.z = hi32(acc[p][2]); o.w = hi32(acc[p][3]);
            } else {
                o.x = lo32(acc[p][0]); o.y = lo32(acc[p][1]); o.z = lo32(acc[p][2]); o.w = lo32(acc[p][3]);
            }
            o.x = fmaxf(o.x + bv.x, 0.f);
            o.y = fmaxf(o.y + bv.y, 0.f);
            o.z = fmaxf(o.z + bv.z, 0.f);
            o.w = fmaxf(o.w + bv.w, 0.f);
            ((float4*)g_h)[row * 32 + tc] = o;
        }
    }
}

// ---------------- pooling: batch is sorted; per-block local accumulation + flush atomics ----
__global__ void k_pool(const void* __restrict__ batch, int N) {
    int c = threadIdx.x;            // 0..127, feature column
    int n0 = blockIdx.x * 128;
    if (n0 >= N) return;
    int n1 = min(n0 + 128, N);
    int curg = idx_at(batch, n0);
    float acc = 0.f, cntacc = 0.f;
    for (int n = n0; n < n1; n++) {
        int g = idx_at(batch, n);
        if (g != curg) {
            atomicAdd(&g_psum[curg * 128 + c], acc);
            if (c == 0) atomicAdd(&g_gcnt[curg], cntacc);
            acc = 0.f; cntacc = 0.f; curg = g;
        }
        acc += g_h[n * 128 + c];
        cntacc += 1.f;
    }
    atomicAdd(&g_psum[curg * 128 + c], acc);
    if (c == 0) atomicAdd(&g_gcnt[curg], cntacc);
}

// ---------------- final FC (128 -> 2) + softmax ----------------
__global__ void k_fc(const float* __restrict__ Wfc, const float* __restrict__ bfc,
                     float* __restrict__ out, int G) {
    int g = blockIdx.x * blockDim.x + threadIdx.x;
    if (g >= G) return;
    float inv = 1.0f / fmaxf(g_gcnt[g], 1.0f);
    float l0 = bfc[0], l1 = bfc[1];
#pragma unroll 8
    for (int c = 0; c < 128; c++) {
        float p = g_psum[g * 128 + c] * inv;
        l0 = fmaf(p, Wfc[2 * c + 0], l0);
        l1 = fmaf(p, Wfc[2 * c + 1], l1);
    }
    float m = fmaxf(l0, l1);
    float e0 = __expf(l0 - m), e1 = __expf(l1 - m);
    float s = e0 + e1;
    out[2 * g + 0] = e0 / s;
    out[2 * g + 1] = e1 / s;
}

// ---------------- launch: ONLY kernel launches, no other runtime APIs ----------------
extern "C" void kernel_launch(void* const* d_in, const int* in_sizes, int n_in,
                              void* d_out, int out_size) {
    const float* x     = (const float*)d_in[0];
    const void*  ei    = d_in[1];
    const void*  batch = d_in[2];

    // Weights identified by SIZE (robust to num_graphs being materialized or not)
    const float *W1 = 0, *b1 = 0, *W2 = 0, *b2 = 0, *Wfc = 0, *bfc = 0;
    for (int i = 3; i < n_in; i++) {
        int s = in_sizes[i];
        const float* p = (const float*)d_in[i];
        if      (s == 8192)  W1 = p;
        else if (s == 16384) W2 = p;
        else if (s == 256)   Wfc = p;
        else if (s == 2)     bfc = p;
        else if (s == 128)   { if (!b1) b1 = p; else b2 = p; }
    }

    int N = in_sizes[2];        // batch has one entry per node
    int E = in_sizes[1] / 2;    // edge_index is [2, E]
    int G = out_size / 2;

    k_detect<<<1, 1>>>((const unsigned*)ei);

    int nzero = N > G * 128 ? N : G * 128;
    k_zero<<<(nzero + 255) / 256, 256>>>(N, G);

    // CSR build (by dst) + norm coefficients
    k_count<<<(E + 255) / 256, 256>>>(ei, E);
    int nb = (N + SCAN_T - 1) / SCAN_T;
    k_scan1<<<nb, SCAN_T>>>(N);
    k_scan2<<<1, 256>>>(nb, N);
    k_scan3<<<nb, SCAN_T>>>(N);
    k_dinv<<<(N + 255) / 256, 256>>>(N);
    k_fill<<<(E + 255) / 256, 256>>>(ei, E);

    int aggBlocks  = (N * 32 + 255) / 256;
    int gemmBlocks = (N + 63) / 64;

    // layer 1: g_y = A_hat x (N x 64), g_h = relu(g_y W1 + b1)
    k_agg<float2, false><<<aggBlocks, 256>>>(x, N);
    k_gemm<64><<<gemmBlocks, 256>>>(W1, b1, N);

    // layer 2: g_y = A_hat g_h (N x 128), g_h = relu(g_y W2 + b2)
    k_agg<float4, true><<<aggBlocks, 256>>>(nullptr, N);
    k_gemm<128><<<gemmBlocks, 256>>>(W2, b2, N);

    // pooling + FC + softmax
    k_pool<<<(N + 127) / 128, 128>>>(batch, N);
    k_fc<<<(G + 127) / 128, 128>>>(Wfc, bfc, (float*)d_out, G);
}

// round 11
// speedup vs baseline: 1.4445x; 1.1147x over previous
#include <cuda_runtime.h>
#include <cuda_bf16.h>

#define MAXN 100000
#define MAXE 1000000
#define MAXG 1024
#define SCAN_T 512

// ---------------- scratch (device globals: no allocation allowed) ----------------
__device__ int   g_idx64;
__device__ int   g_degcnt[MAXN];
__device__ int   g_cursor[MAXN];
__device__ int   g_rowptr[MAXN + 1];
__device__ int   g_bsum[256];
__device__ int   g_col[MAXE];
__device__ float g_dinv[MAXN];
__device__ float g_selfc[MAXN];
__device__ float g_y[MAXN * 128];   // aggregation output (GEMM input)
__device__ float g_h[MAXN * 128];   // GEMM output (h1, then h2)
__device__ float g_psum[MAXG * 128];
__device__ float g_gcnt[MAXG];
// bf16 hi/lo split of W1/W2, TRANSPOSED to [n][k] (B operand, K-major = col-major KxN)
__device__ __nv_bfloat16 g_w1hi[64 * 128],  g_w1lo[64 * 128];
__device__ __nv_bfloat16 g_w2hi[128 * 128], g_w2lo[128 * 128];

// ---------------- generic helpers ----------------
__device__ __forceinline__ void vfma(float4& a, float4 v, float s) {
    a.x = fmaf(v.x, s, a.x); a.y = fmaf(v.y, s, a.y);
    a.z = fmaf(v.z, s, a.z); a.w = fmaf(v.w, s, a.w);
}
__device__ __forceinline__ void vfma(float2& a, float2 v, float s) {
    a.x = fmaf(v.x, s, a.x); a.y = fmaf(v.y, s, a.y);
}
__device__ __forceinline__ float4 vscale(float4 v, float s) { return make_float4(v.x*s, v.y*s, v.z*s, v.w*s); }
__device__ __forceinline__ float2 vscale(float2 v, float s) { return make_float2(v.x*s, v.y*s); }

__device__ __forceinline__ int idx_at(const void* p, int i) {
    return g_idx64 ? (int)((const long long*)p)[i] : ((const int*)p)[i];
}

__device__ __forceinline__ unsigned s2u(const void* p) {
    unsigned a;
    asm("{ .reg .u64 t; cvta.to.shared.u64 t, %1; cvt.u32.u64 %0, t; }" : "=r"(a) : "l"(p));
    return a;
}

__device__ __forceinline__ unsigned packbf(__nv_bfloat16 a, __nv_bfloat16 b) {
    unsigned short ua = *(unsigned short*)&a, ub = *(unsigned short*)&b;
    return (unsigned)ua | ((unsigned)ub << 16);
}
__device__ __forceinline__ void split2(float f0, float f1, unsigned& hi, unsigned& lo) {
    __nv_bfloat16 h0 = __float2bfloat16(f0), h1 = __float2bfloat16(f1);
    float r0 = f0 - __bfloat162float(h0), r1 = f1 - __bfloat162float(h1);
    hi = packbf(h0, h1);
    lo = packbf(__float2bfloat16(r0), __float2bfloat16(r1));
}

// ---------------- mma.sync helpers (plain sm_80+ PTX; works on sm_103 target) ----------------
#define LDM4(r, addr) \
    asm volatile("ldmatrix.sync.aligned.m8n8.x4.shared.b16 {%0,%1,%2,%3}, [%4];" \
        : "=r"((r)[0]), "=r"((r)[1]), "=r"((r)[2]), "=r"((r)[3]) : "r"(addr))

#define MMA_BF16(c, a, b0, b1) \
    asm volatile("mma.sync.aligned.m16n8k16.row.col.f32.bf16.bf16.f32 " \
        "{%0,%1,%2,%3}, {%4,%5,%6,%7}, {%8,%9}, {%0,%1,%2,%3};" \
        : "+f"((c)[0]), "+f"((c)[1]), "+f"((c)[2]), "+f"((c)[3]) \
        : "r"((a)[0]), "r"((a)[1]), "r"((a)[2]), "r"((a)[3]), "r"(b0), "r"(b1))

// ---------------- dtype detection ----------------
__global__ void k_detect(const unsigned* __restrict__ ei) {
    unsigned o = ei[1] | ei[3] | ei[5] | ei[7] | ei[9] | ei[11] | ei[13] | ei[15];
    g_idx64 = (o == 0u) ? 1 : 0;
}

// ---------------- W split: fp32 [k][n] -> bf16 hi/lo transposed [n][k] ----------------
template <int K>
__global__ void k_wsplit(const float* __restrict__ W) {
    int i = blockIdx.x * 256 + threadIdx.x;
    if (i < K * 128) {
        int k = i >> 7, n = i & 127;
        float v = W[i];
        __nv_bfloat16 h = __float2bfloat16(v);
        float r = v - __bfloat162float(h);
        __nv_bfloat16* BH = (K == 64) ? g_w1hi : g_w2hi;
        __nv_bfloat16* BL = (K == 64) ? g_w1lo : g_w2lo;
        BH[n * K + k] = h;
        BL[n * K + k] = __float2bfloat16(r);
    }
}

// ---------------- setup kernels ----------------
__global__ void k_zero(int N, int G) {
    int i = blockIdx.x * blockDim.x + threadIdx.x;
    if (i < N) { g_degcnt[i] = 0; g_cursor[i] = 0; }
    if (i < G * 128) g_psum[i] = 0.f;
    if (i < G) g_gcnt[i] = 0.f;
}

__global__ void k_count(const void* __restrict__ ei, int E) {
    int e = blockIdx.x * blockDim.x + threadIdx.x;
    if (e < E) atomicAdd(&g_degcnt[idx_at(ei, E + e)], 1);
}

__global__ void k_scan1(int N) {
    __shared__ int ss[SCAN_T];
    int tid = threadIdx.x;
    int i = blockIdx.x * SCAN_T + tid;
    ss[tid] = (i < N) ? g_degcnt[i] : 0;
    __syncthreads();
#pragma unroll
    for (int off = SCAN_T / 2; off > 0; off >>= 1) {
        if (tid < off) ss[tid] += ss[tid + off];
        __syncthreads();
    }
    if (tid == 0) g_bsum[blockIdx.x] = ss[0];
}

__global__ void k_scan2(int nb, int N) {
    __shared__ int ss[256];
    int tid = threadIdx.x;
    int v = (tid < nb) ? g_bsum[tid] : 0;
    ss[tid] = v;
    __syncthreads();
#pragma unroll
    for (int off = 1; off < 256; off <<= 1) {
        int t = (tid >= off) ? ss[tid - off] : 0;
        __syncthreads();
        ss[tid] += t;
        __syncthreads();
    }
    if (tid < nb) g_bsum[tid] = ss[tid] - v;
    if (tid == 255) g_rowptr[N] = ss[255];
}

__global__ void k_scan3(int N) {
    __shared__ int ss[SCAN_T];
    int tid = threadIdx.x;
    int i = blockIdx.x * SCAN_T + tid;
    int v = (i < N) ? g_degcnt[i] : 0;
    ss[tid] = v;
    __syncthreads();
#pragma unroll
    for (int off = 1; off < SCAN_T; off <<= 1) {
        int t = (tid >= off) ? ss[tid - off] : 0;
        __syncthreads();
        ss[tid] += t;
        __syncthreads();
    }
    if (i < N) g_rowptr[i] = g_bsum[blockIdx.x] + ss[tid] - v;
}

__global__ void k_dinv(int N) {
    int i = blockIdx.x * blockDim.x + threadIdx.x;
    if (i < N) {
        float d = (float)g_degcnt[i] + 1.0f;
        g_dinv[i]  = rsqrtf(d);
        g_selfc[i] = 1.0f / d;
    }
}

__global__ void k_fill(const void* __restrict__ ei, int E) {
    int e = blockIdx.x * blockDim.x + threadIdx.x;
    if (e < E) {
        int s = idx_at(ei, e);
        int d = idx_at(ei, E + e);
        int pos = g_rowptr[d] + atomicAdd(&g_cursor[d], 1);
        g_col[pos] = s;
    }
}

// ---------------- aggregation (unchanged from passing R8) ----------------
template <typename VecT, bool FROM_GH>
__global__ void k_agg(const float* __restrict__ xin, int N) {
    int t = blockIdx.x * blockDim.x + threadIdx.x;
    int node = t >> 5;
    int lane = t & 31;
    if (node >= N) return;
    const VecT* __restrict__ xv = FROM_GH ? (const VecT*)g_h : (const VecT*)xin;
    VecT a = vscale(xv[node * 32 + lane], g_selfc[node]);
    float di = g_dinv[node];
    int p = g_rowptr[node];
    int e = g_rowptr[node + 1];
    for (; p + 1 < e; p += 2) {
        int s0 = __ldg(&g_col[p]);
        int s1 = __ldg(&g_col[p + 1]);
        float w0 = di * __ldg(&g_dinv[s0]);
        float w1 = di * __ldg(&g_dinv[s1]);
        VecT v0 = xv[s0 * 32 + lane];
        VecT v1 = xv[s1 * 32 + lane];
        vfma(a, v0, w0);
        vfma(a, v1, w1);
    }
    if (p < e) {
        int s0 = __ldg(&g_col[p]);
        vfma(a, xv[s0 * 32 + lane], di * __ldg(&g_dinv[s0]));
    }
    ((VecT*)g_y)[node * 32 + lane] = a;
}

// ---------------- tensor-core GEMM via mma.sync: g_h = relu(g_y[N,K] @ W[K,128] + b) ------
// bf16x3: D = Ahi*Bhi + Ahi*Blo + Alo*Bhi, fp32 accumulators.
// CTA: 128 rows x 128 cols, 8 warps (4x2), warp tile 32x64 (2 m-tiles x 8 n-tiles m16n8k16).
// K chunked by 32; smem rows padded to 40 bf16 (80B) -> conflict-free ldmatrix.
template <int K>
__global__ void __launch_bounds__(256) k_mma(const float* __restrict__ bias, int N) {
    __shared__ __nv_bfloat16 a_hi[128 * 40], a_lo[128 * 40];
    __shared__ __nv_bfloat16 b_hi[128 * 40], b_lo[128 * 40];

    const int tid  = threadIdx.x;
    const int lane = tid & 31;
    const int wid  = tid >> 5;
    const int row0 = blockIdx.x * 128;
    const int mrow0 = (wid >> 1) * 32;   // warp row offset
    const int ncol0 = (wid & 1) * 64;    // warp col offset

    const __nv_bfloat16* whi = (K == 64) ? g_w1hi : g_w2hi;
    const __nv_bfloat16* wlo = (K == 64) ? g_w1lo : g_w2lo;

    float acc[2][8][4];
#pragma unroll
    for (int mt = 0; mt < 2; mt++)
#pragma unroll
        for (int nt = 0; nt < 8; nt++)
#pragma unroll
            for (int j = 0; j < 4; j++) acc[mt][nt][j] = 0.f;

    const unsigned a_hi_u = s2u(a_hi), a_lo_u = s2u(a_lo);
    const unsigned b_hi_u = s2u(b_hi), b_lo_u = s2u(b_lo);

    const int r    = tid >> 1;   // staging row (0..127)
    const int half = tid & 1;    // staging k-half (16 elems each)

    for (int kc = 0; kc < K; kc += 32) {
        __syncthreads();   // previous chunk consumed
        // ---- stage A: fp32 g_y -> bf16 hi/lo ----
        {
            int rowA = row0 + r;
            unsigned dsto = (unsigned)(r * 40 + half * 16) * 2;   // bytes
            if (rowA < N) {
                const float4* src = (const float4*)(g_y + (size_t)rowA * K + kc + half * 16);
#pragma unroll
                for (int j = 0; j < 4; j++) {
                    float4 v = src[j];
                    unsigned h0, l0, h1, l1;
                    split2(v.x, v.y, h0, l0);
                    split2(v.z, v.w, h1, l1);
                    *(uint2*)((char*)a_hi + dsto + j * 8) = make_uint2(h0, h1);
                    *(uint2*)((char*)a_lo + dsto + j * 8) = make_uint2(l0, l1);
                }
            } else {
#pragma unroll
                for (int j = 0; j < 4; j++) {
                    *(uint2*)((char*)a_hi + dsto + j * 8) = make_uint2(0u, 0u);
                    *(uint2*)((char*)a_lo + dsto + j * 8) = make_uint2(0u, 0u);
                }
            }
        }
        // ---- stage B: bf16 [n][K] copy ----
        {
            const uint4* sh = (const uint4*)(whi + (size_t)r * K + kc + half * 16);
            const uint4* sl = (const uint4*)(wlo + (size_t)r * K + kc + half * 16);
            unsigned dsto = (unsigned)(r * 40 + half * 16) * 2;
            *(uint4*)((char*)b_hi + dsto)      = sh[0];
            *(uint4*)((char*)b_hi + dsto + 16) = sh[1];
            *(uint4*)((char*)b_lo + dsto)      = sl[0];
            *(uint4*)((char*)b_lo + dsto + 16) = sl[1];
        }
        __syncthreads();

        const int lr = lane & 15, lc = lane >> 4;
#pragma unroll
        for (int ks = 0; ks < 32; ks += 16) {
            unsigned ah[2][4], al[2][4];
#pragma unroll
            for (int mt = 0; mt < 2; mt++) {
                unsigned ao = (unsigned)((mrow0 + mt * 16 + lr) * 40 + ks + lc * 8) * 2;
                LDM4(ah[mt], a_hi_u + ao);
                LDM4(al[mt], a_lo_u + ao);
            }
#pragma unroll
            for (int np = 0; np < 4; np++) {   // covers n-tiles 2np, 2np+1
                unsigned bo = (unsigned)((ncol0 + np * 16 + lr) * 40 + ks + lc * 8) * 2;
                unsigned bh[4], bl[4];
                LDM4(bh, b_hi_u + bo);
                LDM4(bl, b_lo_u + bo);
#pragma unroll
                for (int sub = 0; sub < 2; sub++) {
                    int nt = 2 * np + sub;
#pragma unroll
                    for (int mt = 0; mt < 2; mt++) {
                        MMA_BF16(acc[mt][nt], ah[mt], bh[sub], bh[sub + 2]);
                        MMA_BF16(acc[mt][nt], ah[mt], bl[sub], bl[sub + 2]);
                        MMA_BF16(acc[mt][nt], al[mt], bh[sub], bh[sub + 2]);
                    }
                }
            }
        }
    }

    // ---- epilogue: bias + relu + store ----
    const int tq  = lane >> 2;        // 0..7 (row within 8)
    const int tc2 = (lane & 3) * 2;   // col pair
#pragma unroll
    for (int mt = 0; mt < 2; mt++) {
        int rowa = row0 + mrow0 + mt * 16 + tq;
        int rowb = rowa + 8;
#pragma unroll
        for (int nt = 0; nt < 8; nt++) {
            int col = ncol0 + nt * 8 + tc2;
            float b0 = __ldg(&bias[col]), b1 = __ldg(&bias[col + 1]);
            const float* c = acc[mt][nt];
            if (rowa < N)
                *(float2*)(g_h + (size_t)rowa * 128 + col) =
                    make_float2(fmaxf(c[0] + b0, 0.f), fmaxf(c[1] + b1, 0.f));
            if (rowb < N)
                *(float2*)(g_h + (size_t)rowb * 128 + col) =
                    make_float2(fmaxf(c[2] + b0, 0.f), fmaxf(c[3] + b1, 0.f));
        }
    }
}

// ---------------- pooling (unchanged) ----------------
__global__ void k_pool(const void* __restrict__ batch, int N) {
    int c = threadIdx.x;
    int n0 = blockIdx.x * 128;
    if (n0 >= N) return;
    int n1 = min(n0 + 128, N);
    int curg = idx_at(batch, n0);
    float acc = 0.f, cntacc = 0.f;
    for (int n = n0; n < n1; n++) {
        int g = idx_at(batch, n);
        if (g != curg) {
            atomicAdd(&g_psum[curg * 128 + c], acc);
            if (c == 0) atomicAdd(&g_gcnt[curg], cntacc);
            acc = 0.f; cntacc = 0.f; curg = g;
        }
        acc += g_h[n * 128 + c];
        cntacc += 1.f;
    }
    atomicAdd(&g_psum[curg * 128 + c], acc);
    if (c == 0) atomicAdd(&g_gcnt[curg], cntacc);
}

// ---------------- final FC + softmax (unchanged) ----------------
__global__ void k_fc(const float* __restrict__ Wfc, const float* __restrict__ bfc,
                     float* __restrict__ out, int G) {
    int g = blockIdx.x * blockDim.x + threadIdx.x;
    if (g >= G) return;
    float inv = 1.0f / fmaxf(g_gcnt[g], 1.0f);
    float l0 = bfc[0], l1 = bfc[1];
#pragma unroll 8
    for (int c = 0; c < 128; c++) {
        float p = g_psum[g * 128 + c] * inv;
        l0 = fmaf(p, Wfc[2 * c + 0], l0);
        l1 = fmaf(p, Wfc[2 * c + 1], l1);
    }
    float m = fmaxf(l0, l1);
    float e0 = __expf(l0 - m), e1 = __expf(l1 - m);
    float s = e0 + e1;
    out[2 * g + 0] = e0 / s;
    out[2 * g + 1] = e1 / s;
}

// ---------------- launch: ONLY kernel launches ----------------
extern "C" void kernel_launch(void* const* d_in, const int* in_sizes, int n_in,
                              void* d_out, int out_size) {
    const float* x     = (const float*)d_in[0];
    const void*  ei    = d_in[1];
    const void*  batch = d_in[2];

    const float *W1 = 0, *b1 = 0, *W2 = 0, *b2 = 0, *Wfc = 0, *bfc = 0;
    for (int i = 3; i < n_in; i++) {
        int s = in_sizes[i];
        const float* p = (const float*)d_in[i];
        if      (s == 8192)  W1 = p;
        else if (s == 16384) W2 = p;
        else if (s == 256)   Wfc = p;
        else if (s == 2)     bfc = p;
        else if (s == 128)   { if (!b1) b1 = p; else b2 = p; }
    }

    int N = in_sizes[2];
    int E = in_sizes[1] / 2;
    int G = out_size / 2;

    k_detect<<<1, 1>>>((const unsigned*)ei);

    int nzero = N > G * 128 ? N : G * 128;
    k_zero<<<(nzero + 255) / 256, 256>>>(N, G);

    k_count<<<(E + 255) / 256, 256>>>(ei, E);
    int nb = (N + SCAN_T - 1) / SCAN_T;
    k_scan1<<<nb, SCAN_T>>>(N);
    k_scan2<<<1, 256>>>(nb, N);
    k_scan3<<<nb, SCAN_T>>>(N);
    k_dinv<<<(N + 255) / 256, 256>>>(N);
    k_fill<<<(E + 255) / 256, 256>>>(ei, E);

    k_wsplit<64><<<32, 256>>>(W1);
    k_wsplit<128><<<64, 256>>>(W2);

    int aggBlocks = (N * 32 + 255) / 256;
    int mmaBlocks = (N + 127) / 128;

    // layer 1: g_y = A_hat x (N x 64), g_h = relu(g_y W1 + b1)
    k_agg<float2, false><<<aggBlocks, 256>>>(x, N);
    k_mma<64><<<mmaBlocks, 256>>>(b1, N);

    // layer 2: g_y = A_hat g_h (N x 128), g_h = relu(g_y W2 + b2)
    k_agg<float4, true><<<aggBlocks, 256>>>(nullptr, N);
    k_mma<128><<<mmaBlocks, 256>>>(b2, N);

    // pooling + FC + softmax
    k_pool<<<(N + 127) / 128, 128>>>(batch, N);
    k_fc<<<(G + 127) / 128, 128>>>(Wfc, bfc, (float*)d_out, G);
}

// round 12
// speedup vs baseline: 1.5636x; 1.0825x over previous
#include <cuda_runtime.h>
#include <cuda_bf16.h>

#define MAXN 100000
#define MAXE 1000000
#define MAXG 1024
#define SCAN_T 512

// ---------------- scratch (device globals: no allocation allowed) ----------------
__device__ int   g_idx64;
__device__ int   g_degcnt[MAXN];
__device__ int   g_cursor[MAXN];
__device__ int   g_rowptr[MAXN + 1];
__device__ int   g_bsum[256];
__device__ int   g_col[MAXE];
__device__ float g_dinv[MAXN];
__device__ float g_selfc[MAXN];
__device__ float g_y[MAXN * 128];   // aggregation output (GEMM input)
__device__ float g_h[MAXN * 128];   // layer-1 GEMM output (h1)
__device__ float g_psum[MAXG * 128];
__device__ float g_gcnt[MAXG];
// bf16 hi/lo split of W1/W2, TRANSPOSED to [n][k] (B operand, K-major)
__device__ __nv_bfloat16 g_w1hi[64 * 128],  g_w1lo[64 * 128];
__device__ __nv_bfloat16 g_w2hi[128 * 128], g_w2lo[128 * 128];

// ---------------- generic helpers ----------------
__device__ __forceinline__ void vfma(float4& a, float4 v, float s) {
    a.x = fmaf(v.x, s, a.x); a.y = fmaf(v.y, s, a.y);
    a.z = fmaf(v.z, s, a.z); a.w = fmaf(v.w, s, a.w);
}
__device__ __forceinline__ void vfma(float2& a, float2 v, float s) {
    a.x = fmaf(v.x, s, a.x); a.y = fmaf(v.y, s, a.y);
}
__device__ __forceinline__ float4 vscale(float4 v, float s) { return make_float4(v.x*s, v.y*s, v.z*s, v.w*s); }
__device__ __forceinline__ float2 vscale(float2 v, float s) { return make_float2(v.x*s, v.y*s); }

__device__ __forceinline__ int idx_at(const void* p, int i) {
    return g_idx64 ? (int)((const long long*)p)[i] : ((const int*)p)[i];
}

__device__ __forceinline__ unsigned s2u(const void* p) {
    unsigned a;
    asm("{ .reg .u64 t; cvta.to.shared.u64 t, %1; cvt.u32.u64 %0, t; }" : "=r"(a) : "l"(p));
    return a;
}

__device__ __forceinline__ unsigned packbf(__nv_bfloat16 a, __nv_bfloat16 b) {
    unsigned short ua = *(unsigned short*)&a, ub = *(unsigned short*)&b;
    return (unsigned)ua | ((unsigned)ub << 16);
}
__device__ __forceinline__ void split2(float f0, float f1, unsigned& hi, unsigned& lo) {
    __nv_bfloat16 h0 = __float2bfloat16(f0), h1 = __float2bfloat16(f1);
    float r0 = f0 - __bfloat162float(h0), r1 = f1 - __bfloat162float(h1);
    hi = packbf(h0, h1);
    lo = packbf(__float2bfloat16(r0), __float2bfloat16(r1));
}

// ---------------- mma.sync helpers (plain sm_80+ PTX) ----------------
#define LDM4(r, addr) \
    asm volatile("ldmatrix.sync.aligned.m8n8.x4.shared.b16 {%0,%1,%2,%3}, [%4];" \
        : "=r"((r)[0]), "=r"((r)[1]), "=r"((r)[2]), "=r"((r)[3]) : "r"(addr))

#define MMA_BF16(c, a, b0, b1) \
    asm volatile("mma.sync.aligned.m16n8k16.row.col.f32.bf16.bf16.f32 " \
        "{%0,%1,%2,%3}, {%4,%5,%6,%7}, {%8,%9}, {%0,%1,%2,%3};" \
        : "+f"((c)[0]), "+f"((c)[1]), "+f"((c)[2]), "+f"((c)[3]) \
        : "r"((a)[0]), "r"((a)[1]), "r"((a)[2]), "r"((a)[3]), "r"(b0), "r"(b1))

// ---------------- dtype detection + small-buffer zeroing (1 block) ----------------
__global__ void k_detect(const unsigned* __restrict__ ei, int G) {
    int tid = threadIdx.x;
    if (tid == 0) {
        unsigned o = ei[1] | ei[3] | ei[5] | ei[7] | ei[9] | ei[11] | ei[13] | ei[15];
        g_idx64 = (o == 0u) ? 1 : 0;
    }
    for (int i = tid; i < G * 128; i += 1024) g_psum[i] = 0.f;
    for (int i = tid; i < G; i += 1024) g_gcnt[i] = 0.f;
}

// ---------------- zero deg/cursor + count nodes per graph ----------------
__global__ void k_zero(const void* __restrict__ batch, int N) {
    int i = blockIdx.x * blockDim.x + threadIdx.x;
    if (i < N) {
        g_degcnt[i] = 0;
        g_cursor[i] = 0;
        atomicAdd(&g_gcnt[idx_at(batch, i)], 1.f);
    }
}

// ---------------- W split: fp32 [k][n] -> bf16 hi/lo transposed [n][k], both layers ----
__global__ void k_wsplit(const float* __restrict__ W1, const float* __restrict__ W2) {
    int i = blockIdx.x * 256 + threadIdx.x;
    if (i < 64 * 128) {
        int k = i >> 7, n = i & 127;
        float v = W1[i];
        __nv_bfloat16 h = __float2bfloat16(v);
        g_w1hi[n * 64 + k] = h;
        g_w1lo[n * 64 + k] = __float2bfloat16(v - __bfloat162float(h));
    } else if (i < 64 * 128 + 128 * 128) {
        int j = i - 64 * 128;
        int k = j >> 7, n = j & 127;
        float v = W2[j];
        __nv_bfloat16 h = __float2bfloat16(v);
        g_w2hi[n * 128 + k] = h;
        g_w2lo[n * 128 + k] = __float2bfloat16(v - __bfloat162float(h));
    }
}

// ---------------- edge counting ----------------
__global__ void k_count(const void* __restrict__ ei, int E) {
    int e = blockIdx.x * blockDim.x + threadIdx.x;
    if (e < E) atomicAdd(&g_degcnt[idx_at(ei, E + e)], 1);
}

// ---------------- device-wide exclusive scan ----------------
__global__ void k_scan1(int N) {
    __shared__ int ss[SCAN_T];
    int tid = threadIdx.x;
    int i = blockIdx.x * SCAN_T + tid;
    ss[tid] = (i < N) ? g_degcnt[i] : 0;
    __syncthreads();
#pragma unroll
    for (int off = SCAN_T / 2; off > 0; off >>= 1) {
        if (tid < off) ss[tid] += ss[tid + off];
        __syncthreads();
    }
    if (tid == 0) g_bsum[blockIdx.x] = ss[0];
}

__global__ void k_scan2(int nb, int N) {
    __shared__ int ss[256];
    int tid = threadIdx.x;
    int v = (tid < nb) ? g_bsum[tid] : 0;
    ss[tid] = v;
    __syncthreads();
#pragma unroll
    for (int off = 1; off < 256; off <<= 1) {
        int t = (tid >= off) ? ss[tid - off] : 0;
        __syncthreads();
        ss[tid] += t;
        __syncthreads();
    }
    if (tid < nb) g_bsum[tid] = ss[tid] - v;
    if (tid == 255) g_rowptr[N] = ss[255];
}

// phase 3 + degree-derived coefficients (k_dinv folded in)
__global__ void k_scan3(int N) {
    __shared__ int ss[SCAN_T];
    int tid = threadIdx.x;
    int i = blockIdx.x * SCAN_T + tid;
    int v = (i < N) ? g_degcnt[i] : 0;
    ss[tid] = v;
    __syncthreads();
#pragma unroll
    for (int off = 1; off < SCAN_T; off <<= 1) {
        int t = (tid >= off) ? ss[tid - off] : 0;
        __syncthreads();
        ss[tid] += t;
        __syncthreads();
    }
    if (i < N) {
        g_rowptr[i] = g_bsum[blockIdx.x] + ss[tid] - v;
        float d = (float)v + 1.0f;
        g_dinv[i]  = rsqrtf(d);
        g_selfc[i] = 1.0f / d;
    }
}

__global__ void k_fill(const void* __restrict__ ei, int E) {
    int e = blockIdx.x * blockDim.x + threadIdx.x;
    if (e < E) {
        int s = idx_at(ei, e);
        int d = idx_at(ei, E + e);
        int pos = g_rowptr[d] + atomicAdd(&g_cursor[d], 1);
        g_col[pos] = s;
    }
}

// ---------------- aggregation (edge loop unrolled x4 for MLP) ----------------
template <typename VecT, bool FROM_GH>
__global__ void k_agg(const float* __restrict__ xin, int N) {
    int t = blockIdx.x * blockDim.x + threadIdx.x;
    int node = t >> 5;
    int lane = t & 31;
    if (node >= N) return;
    const VecT* __restrict__ xv = FROM_GH ? (const VecT*)g_h : (const VecT*)xin;
    VecT a = vscale(xv[node * 32 + lane], g_selfc[node]);
    float di = g_dinv[node];
    int p = g_rowptr[node];
    int e = g_rowptr[node + 1];
    for (; p + 4 <= e; p += 4) {
        int s0 = __ldg(&g_col[p]);
        int s1 = __ldg(&g_col[p + 1]);
        int s2 = __ldg(&g_col[p + 2]);
        int s3 = __ldg(&g_col[p + 3]);
        float w0 = di * __ldg(&g_dinv[s0]);
        float w1 = di * __ldg(&g_dinv[s1]);
        float w2 = di * __ldg(&g_dinv[s2]);
        float w3 = di * __ldg(&g_dinv[s3]);
        VecT v0 = xv[s0 * 32 + lane];
        VecT v1 = xv[s1 * 32 + lane];
        VecT v2 = xv[s2 * 32 + lane];
        VecT v3 = xv[s3 * 32 + lane];
        vfma(a, v0, w0);
        vfma(a, v1, w1);
        vfma(a, v2, w2);
        vfma(a, v3, w3);
    }
    for (; p < e; p++) {
        int s0 = __ldg(&g_col[p]);
        vfma(a, xv[s0 * 32 + lane], di * __ldg(&g_dinv[s0]));
    }
    ((VecT*)g_y)[node * 32 + lane] = a;
}

// ---------------- tensor-core GEMM via mma.sync ----------------
// g: relu(g_y[N,K] @ W[K,128] + b). bf16x3: D = Ahi*Bhi + Ahi*Blo + Alo*Bhi.
// CTA 128x128, 8 warps (4x2), warp tile 32x64. K chunked by 32, smem row pitch 40 bf16.
// POOL: instead of writing g_h, pool bias+relu'd rows into g_psum (batch sorted).
template <int K, bool POOL>
__global__ void __launch_bounds__(256) k_mma(const float* __restrict__ bias,
                                             const void* __restrict__ batch, int N) {
    __shared__ __align__(16) char smraw[40960];   // 4 x (128 x 40) bf16 tiles; reused as fp32 pool buf
    __nv_bfloat16* a_hi = (__nv_bfloat16*)(smraw);
    __nv_bfloat16* a_lo = (__nv_bfloat16*)(smraw + 10240);
    __nv_bfloat16* b_hi = (__nv_bfloat16*)(smraw + 20480);
    __nv_bfloat16* b_lo = (__nv_bfloat16*)(smraw + 30720);
    float* ps = (float*)smraw;                    // [64][132] fp32, pool staging

    const int tid  = threadIdx.x;
    const int lane = tid & 31;
    const int wid  = tid >> 5;
    const int row0 = blockIdx.x * 128;
    const int mrow0 = (wid >> 1) * 32;
    const int ncol0 = (wid & 1) * 64;

    const __nv_bfloat16* whi = (K == 64) ? g_w1hi : g_w2hi;
    const __nv_bfloat16* wlo = (K == 64) ? g_w1lo : g_w2lo;

    float acc[2][8][4];
#pragma unroll
    for (int mt = 0; mt < 2; mt++)
#pragma unroll
        for (int nt = 0; nt < 8; nt++)
#pragma unroll
            for (int j = 0; j < 4; j++) acc[mt][nt][j] = 0.f;

    const unsigned a_hi_u = s2u(a_hi), a_lo_u = s2u(a_lo);
    const unsigned b_hi_u = s2u(b_hi), b_lo_u = s2u(b_lo);

    const int r    = tid >> 1;
    const int half = tid & 1;

    for (int kc = 0; kc < K; kc += 32) {
        __syncthreads();
        // stage A: fp32 g_y -> bf16 hi/lo
        {
            int rowA = row0 + r;
            unsigned dsto = (unsigned)(r * 40 + half * 16) * 2;
            if (rowA < N) {
                const float4* src = (const float4*)(g_y + (size_t)rowA * K + kc + half * 16);
#pragma unroll
                for (int j = 0; j < 4; j++) {
                    float4 v = src[j];
                    unsigned h0, l0, h1, l1;
                    split2(v.x, v.y, h0, l0);
                    split2(v.z, v.w, h1, l1);
                    *(uint2*)((char*)a_hi + dsto + j * 8) = make_uint2(h0, h1);
                    *(uint2*)((char*)a_lo + dsto + j * 8) = make_uint2(l0, l1);
                }
            } else {
#pragma unroll
                for (int j = 0; j < 4; j++) {
                    *(uint2*)((char*)a_hi + dsto + j * 8) = make_uint2(0u, 0u);
                    *(uint2*)((char*)a_lo + dsto + j * 8) = make_uint2(0u, 0u);
                }
            }
        }
        // stage B
        {
            const uint4* sh = (const uint4*)(whi + (size_t)r * K + kc + half * 16);
            const uint4* sl = (const uint4*)(wlo + (size_t)r * K + kc + half * 16);
            unsigned dsto = (unsigned)(r * 40 + half * 16) * 2;
            *(uint4*)((char*)b_hi + dsto)      = sh[0];
            *(uint4*)((char*)b_hi + dsto + 16) = sh[1];
            *(uint4*)((char*)b_lo + dsto)      = sl[0];
            *(uint4*)((char*)b_lo + dsto + 16) = sl[1];
        }
        __syncthreads();

        const int lr = lane & 15, lc = lane >> 4;
#pragma unroll
        for (int ks = 0; ks < 32; ks += 16) {
            unsigned ah[2][4], al[2][4];
#pragma unroll
            for (int mt = 0; mt < 2; mt++) {
                unsigned ao = (unsigned)((mrow0 + mt * 16 + lr) * 40 + ks + lc * 8) * 2;
                LDM4(ah[mt], a_hi_u + ao);
                LDM4(al[mt], a_lo_u + ao);
            }
#pragma unroll
            for (int np = 0; np < 4; np++) {
                unsigned bo = (unsigned)((ncol0 + np * 16 + lr) * 40 + ks + lc * 8) * 2;
                unsigned bh[4], bl[4];
                LDM4(bh, b_hi_u + bo);
                LDM4(bl, b_lo_u + bo);
#pragma unroll
                for (int sub = 0; sub < 2; sub++) {
                    int nt = 2 * np + sub;
#pragma unroll
                    for (int mt = 0; mt < 2; mt++) {
                        MMA_BF16(acc[mt][nt], ah[mt], bh[sub], bh[sub + 2]);
                        MMA_BF16(acc[mt][nt], ah[mt], bl[sub], bl[sub + 2]);
                        MMA_BF16(acc[mt][nt], al[mt], bh[sub], bh[sub + 2]);
                    }
                }
            }
        }
    }

    const int tq  = lane >> 2;        // 0..7 row in 8
    const int tc2 = (lane & 3) * 2;   // col pair

    if (!POOL) {
        // epilogue: bias + relu + store to g_h
#pragma unroll
        for (int mt = 0; mt < 2; mt++) {
            int rowa = row0 + mrow0 + mt * 16 + tq;
            int rowb = rowa + 8;
#pragma unroll
            for (int nt = 0; nt < 8; nt++) {
                int col = ncol0 + nt * 8 + tc2;
                float b0 = __ldg(&bias[col]), b1 = __ldg(&bias[col + 1]);
                const float* c = acc[mt][nt];
                if (rowa < N)
                    *(float2*)(g_h + (size_t)rowa * 128 + col) =
                        make_float2(fmaxf(c[0] + b0, 0.f), fmaxf(c[1] + b1, 0.f));
                if (rowb < N)
                    *(float2*)(g_h + (size_t)rowb * 128 + col) =
                        make_float2(fmaxf(c[2] + b0, 0.f), fmaxf(c[3] + b1, 0.f));
            }
        }
    } else {
        // fused pooling: two 64-row passes through smem, per-graph flush atomics
#pragma unroll
        for (int P = 0; P < 2; P++) {
            __syncthreads();   // smem tiles (or previous ps pass) fully consumed
            if ((mrow0 >> 6) == P) {
                int baseR = mrow0 & 63;
#pragma unroll
                for (int mt = 0; mt < 2; mt++) {
                    int ra = baseR + mt * 16 + tq;
                    int rb = ra + 8;
#pragma unroll
                    for (int nt = 0; nt < 8; nt++) {
                        int col = ncol0 + nt * 8 + tc2;
                        float b0 = __ldg(&bias[col]), b1 = __ldg(&bias[col + 1]);
                        const float* c = acc[mt][nt];
                        ps[ra * 132 + col]     = fmaxf(c[0] + b0, 0.f);
                        ps[ra * 132 + col + 1] = fmaxf(c[1] + b1, 0.f);
                        ps[rb * 132 + col]     = fmaxf(c[2] + b0, 0.f);
                        ps[rb * 132 + col + 1] = fmaxf(c[3] + b1, 0.f);
                    }
                }
            }
            __syncthreads();
            // pool: 256 threads = 128 cols x 2 row-halves of 32
            int c  = tid & 127;
            int rh = tid >> 7;
            int curg = -1;
            float acc2 = 0.f;
            for (int rr = rh * 32; rr < rh * 32 + 32; rr++) {
                int row = row0 + P * 64 + rr;
                if (row >= N) break;
                int g = idx_at(batch, row);
                if (g != curg) {
                    if (curg >= 0) atomicAdd(&g_psum[curg * 128 + c], acc2);
                    curg = g; acc2 = 0.f;
                }
                acc2 += ps[rr * 132 + c];
            }
            if (curg >= 0) atomicAdd(&g_psum[curg * 128 + c], acc2);
        }
    }
}

// ---------------- final FC (128 -> 2) + softmax ----------------
__global__ void k_fc(const float* __restrict__ Wfc, const float* __restrict__ bfc,
                     float* __restrict__ out, int G) {
    int g = blockIdx.x * blockDim.x + threadIdx.x;
    if (g >= G) return;
    float inv = 1.0f / fmaxf(g_gcnt[g], 1.0f);
    float l0 = bfc[0], l1 = bfc[1];
#pragma unroll 8
    for (int c = 0; c < 128; c++) {
        float p = g_psum[g * 128 + c] * inv;
        l0 = fmaf(p, Wfc[2 * c + 0], l0);
        l1 = fmaf(p, Wfc[2 * c + 1], l1);
    }
    float m = fmaxf(l0, l1);
    float e0 = __expf(l0 - m), e1 = __expf(l1 - m);
    float s = e0 + e1;
    out[2 * g + 0] = e0 / s;
    out[2 * g + 1] = e1 / s;
}

// ---------------- launch: ONLY kernel launches ----------------
extern "C" void kernel_launch(void* const* d_in, const int* in_sizes, int n_in,
                              void* d_out, int out_size) {
    const float* x     = (const float*)d_in[0];
    const void*  ei    = d_in[1];
    const void*  batch = d_in[2];

    const float *W1 = 0, *b1 = 0, *W2 = 0, *b2 = 0, *Wfc = 0, *bfc = 0;
    for (int i = 3; i < n_in; i++) {
        int s = in_sizes[i];
        const float* p = (const float*)d_in[i];
        if      (s == 8192)  W1 = p;
        else if (s == 16384) W2 = p;
        else if (s == 256)   Wfc = p;
        else if (s == 2)     bfc = p;
        else if (s == 128)   { if (!b1) b1 = p; else b2 = p; }
    }

    int N = in_sizes[2];
    int E = in_sizes[1] / 2;
    int G = out_size / 2;

    k_detect<<<1, 1024>>>((const unsigned*)ei, G);
    k_zero<<<(N + 255) / 256, 256>>>(batch, N);
    k_wsplit<<<96, 256>>>(W1, W2);

    k_count<<<(E + 255) / 256, 256>>>(ei, E);
    int nb = (N + SCAN_T - 1) / SCAN_T;
    k_scan1<<<nb, SCAN_T>>>(N);
    k_scan2<<<1, 256>>>(nb, N);
    k_scan3<<<nb, SCAN_T>>>(N);
    k_fill<<<(E + 255) / 256, 256>>>(ei, E);

    int aggBlocks = (N * 32 + 255) / 256;
    int mmaBlocks = (N + 127) / 128;

    // layer 1: g_y = A_hat x (N x 64), g_h = relu(g_y W1 + b1)
    k_agg<float2, false><<<aggBlocks, 256>>>(x, N);
    k_mma<64, false><<<mmaBlocks, 256>>>(b1, batch, N);

    // layer 2: g_y = A_hat g_h (N x 128), pooled relu(g_y W2 + b2) -> g_psum
    k_agg<float4, true><<<aggBlocks, 256>>>(nullptr, N);
    k_mma<128, true><<<mmaBlocks, 256>>>(b2, batch, N);

    // FC + softmax
    k_fc<<<(G + 127) / 128, 128>>>(Wfc, bfc, (float*)d_out, G);
}